// round 1
// baseline (speedup 1.0000x reference)
#include <cuda_runtime.h>

#define T_STEPS 4096
#define HID     1000
#define VOC     32000
#define G_CTAS  125     // 125 CTAs * 8 rows = 1000 rows of h
#define GM      4097    // rows of all_h / output

// Scratch (allocation-free rule: __device__ globals)
__device__ __align__(256) float    g_xseq[T_STEPS * HID];
__device__ __align__(256) float    g_allh[(T_STEPS + 1) * HID];
__device__ unsigned g_flags[G_CTAS];

__device__ __forceinline__ unsigned ld_acquire(const unsigned* p) {
    unsigned v;
    asm volatile("ld.acquire.gpu.u32 %0, [%1];" : "=r"(v) : "l"(p) : "memory");
    return v;
}
__device__ __forceinline__ void st_release(unsigned* p, unsigned v) {
    asm volatile("st.release.gpu.u32 [%0], %1;" :: "l"(p), "r"(v) : "memory");
}

// ---------------------------------------------------------------------------
// Kernel 1: gather x_seq = W_xh[:, tok[t]]  (+ init all_h[0], reset flags)
// ---------------------------------------------------------------------------
__global__ void gather_kernel(const int* __restrict__ tok,
                              const float* __restrict__ Wxh,
                              const float* __restrict__ h0) {
    int i = blockIdx.x * blockDim.x + threadIdx.x;
    if (i < T_STEPS * HID) {
        int t = i / HID;
        int h = i - t * HID;
        g_xseq[i] = __ldg(&Wxh[(long long)h * VOC + tok[t]]);
    }
    if (i < HID)    g_allh[i]  = h0[i];
    if (i < G_CTAS) g_flags[i] = 0u;
}

// ---------------------------------------------------------------------------
// Kernel 2: persistent RNN scan. 125 CTAs, 256 threads. Warp w owns row 8g+w.
// Weights live in registers; h broadcast via global (L2) + flag release/acquire.
// ---------------------------------------------------------------------------
__global__ __launch_bounds__(256, 1)
void scan_kernel(const float* __restrict__ Whh,
                 const float* __restrict__ Bh) {
    __shared__ float hs[1024];             // zero-padded h (1000 -> 1024)
    const int g    = blockIdx.x;
    const int tid  = threadIdx.x;
    const int warp = tid >> 5;
    const int lane = tid & 31;
    const int row  = g * 8 + warp;         // < 1000 always

    // Preload this row's weights: lane handles k = 4*lane + q + 128*j
    float w[8][4];
#pragma unroll
    for (int j = 0; j < 8; j++)
#pragma unroll
        for (int q = 0; q < 4; q++) {
            int k = 4 * lane + q + 128 * j;
            w[j][q] = (k < HID) ? __ldg(&Whh[row * HID + k]) : 0.0f;
        }
    const float bias = __ldg(&Bh[row]);
    const float4* __restrict__ allh4 = (const float4*)g_allh;  // 250 float4 / row

    for (int t = 0; t < T_STEPS; t++) {
        // Wait until every CTA has published step t (step 0 published by gather)
        if (t > 0 && tid < G_CTAS) {
            while (ld_acquire(&g_flags[tid]) < (unsigned)t) { }
        }
        __syncthreads();   // also protects hs reuse across iterations

        float xv = 0.0f;
        if (lane == 0) xv = __ldg(&g_xseq[t * HID + row]);

        // Stage h_t into shared (bypass L1: written by other SMs)
        if (tid < 250) {
            ((float4*)hs)[tid] = __ldcg(allh4 + (size_t)t * 250 + tid);
        } else {
            ((float4*)hs)[tid] = make_float4(0.f, 0.f, 0.f, 0.f); // pad 1000..1023
        }
        __syncthreads();

        float a0 = 0.f, a1 = 0.f, a2 = 0.f, a3 = 0.f;
#pragma unroll
        for (int j = 0; j < 8; j++) {
            float4 hv = ((const float4*)hs)[lane + 32 * j];
            a0 = fmaf(w[j][0], hv.x, a0);
            a1 = fmaf(w[j][1], hv.y, a1);
            a2 = fmaf(w[j][2], hv.z, a2);
            a3 = fmaf(w[j][3], hv.w, a3);
        }
        float acc = (a0 + a1) + (a2 + a3);
#pragma unroll
        for (int s = 16; s > 0; s >>= 1)
            acc += __shfl_xor_sync(0xffffffffu, acc, s);

        if (lane == 0) {
            float y = tanhf(acc + xv + bias);
            g_allh[(size_t)(t + 1) * HID + row] = y;
        }
        __syncthreads();                       // all 8 row-stores done (CTA scope)
        if (tid == 0) st_release(&g_flags[g], (unsigned)(t + 1));  // cumulative release
    }
}

// ---------------------------------------------------------------------------
// Kernel 3: out = all_h (4097x1000) @ W_hy^T (W_hy is 32000x1000, K-contiguous)
// 128x128x8 tile, 256 threads, 8x8 register tile (4+4 split for bank-free LDS).
// ---------------------------------------------------------------------------
__global__ __launch_bounds__(256, 2)
void gemm_kernel(const float* __restrict__ Why, float* __restrict__ C) {
    __shared__ float As[8][132];   // +4 pad -> conflict-free transposed stores
    __shared__ float Bs[8][132];
    const int tid = threadIdx.x;
    const int m0 = blockIdx.x * 128;   // m fastest: all_h stays L2-resident
    const int n0 = blockIdx.y * 128;
    const int lr = tid >> 1;
    const int lk = (tid & 1) * 4;
    const int tx = tid & 15;
    const int ty = tid >> 4;

    const float* Aptr = g_allh + (size_t)(m0 + lr) * HID + lk;
    const float* Bptr = Why    + (size_t)(n0 + lr) * HID + lk;
    const bool av = (m0 + lr) < GM;

    float acc[8][8];
#pragma unroll
    for (int i = 0; i < 8; i++)
#pragma unroll
        for (int j = 0; j < 8; j++) acc[i][j] = 0.f;

    for (int k0 = 0; k0 < HID; k0 += 8) {
        float4 a4 = av ? *(const float4*)(Aptr + k0) : make_float4(0.f,0.f,0.f,0.f);
        float4 b4 =      *(const float4*)(Bptr + k0);
        __syncthreads();
        As[lk+0][lr] = a4.x; As[lk+1][lr] = a4.y; As[lk+2][lr] = a4.z; As[lk+3][lr] = a4.w;
        Bs[lk+0][lr] = b4.x; Bs[lk+1][lr] = b4.y; Bs[lk+2][lr] = b4.z; Bs[lk+3][lr] = b4.w;
        __syncthreads();
#pragma unroll
        for (int kk = 0; kk < 8; kk++) {
            float a[8], b[8];
            *(float4*)&a[0] = *(const float4*)&As[kk][ty * 4];
            *(float4*)&a[4] = *(const float4*)&As[kk][64 + ty * 4];
            *(float4*)&b[0] = *(const float4*)&Bs[kk][tx * 4];
            *(float4*)&b[4] = *(const float4*)&Bs[kk][64 + tx * 4];
#pragma unroll
            for (int i = 0; i < 8; i++)
#pragma unroll
                for (int j = 0; j < 8; j++)
                    acc[i][j] = fmaf(a[i], b[j], acc[i][j]);
        }
    }

#pragma unroll
    for (int ih = 0; ih < 2; ih++)
#pragma unroll
        for (int i = 0; i < 4; i++) {
            int row = m0 + ih * 64 + ty * 4 + i;
            if (row < GM) {
                float* cp = C + (size_t)row * VOC + n0 + tx * 4;
                int r = ih * 4 + i;
                *(float4*)cp        = make_float4(acc[r][0], acc[r][1], acc[r][2], acc[r][3]);
                *(float4*)(cp + 64) = make_float4(acc[r][4], acc[r][5], acc[r][6], acc[r][7]);
            }
        }
}

// ---------------------------------------------------------------------------
extern "C" void kernel_launch(void* const* d_in, const int* in_sizes, int n_in,
                              void* d_out, int out_size) {
    const int*   tok = (const int*)  d_in[0];
    const float* h0  = (const float*)d_in[1];
    const float* Wxh = (const float*)d_in[2];
    const float* Whh = (const float*)d_in[3];
    const float* Why = (const float*)d_in[4];
    const float* Bh  = (const float*)d_in[5];
    float* out = (float*)d_out;

    gather_kernel<<<(T_STEPS * HID + 255) / 256, 256>>>(tok, Wxh, h0);
    scan_kernel<<<G_CTAS, 256>>>(Whh, Bh);
    dim3 ggrid(33, 250);   // ceil(4097/128) x (32000/128), m fastest
    gemm_kernel<<<ggrid, 256>>>(Why, out);
}

// round 3
// speedup vs baseline: 1.1215x; 1.1215x over previous
#include <cuda_runtime.h>
#include <cuda_bf16.h>
#include <cstdint>

#define T_STEPS 4096
#define HID     1000
#define VOC     32000
#define G_CTAS  125
#define GM      4097
#define KP      1024            // padded K
#define KAUG    3072            // augmented K (3 bf16 split terms)
#define MPAD    4224            // 33 * 128

// ---------------- device scratch (allocation-free rule) ----------------
__device__ __align__(256) float          g_xseq[T_STEPS * HID];
__device__ __align__(256) float          g_allh[(T_STEPS + 1) * HID];
__device__ __align__(1024) __nv_bfloat16 g_A2[(size_t)MPAD * KAUG];
__device__ __align__(1024) __nv_bfloat16 g_B2[(size_t)VOC  * KAUG];
__device__ unsigned g_flags[G_CTAS];

__device__ __forceinline__ unsigned ld_acquire(const unsigned* p) {
    unsigned v;
    asm volatile("ld.acquire.gpu.u32 %0, [%1];" : "=r"(v) : "l"(p) : "memory");
    return v;
}
__device__ __forceinline__ void st_release(unsigned* p, unsigned v) {
    asm volatile("st.release.gpu.u32 [%0], %1;" :: "l"(p), "r"(v) : "memory");
}
__device__ __forceinline__ uint32_t smem_u32(const void* p) {
    uint32_t a;
    asm("{ .reg .u64 t; cvta.to.shared.u64 t, %1; cvt.u32.u64 %0, t; }" : "=r"(a) : "l"(p));
    return a;
}
#define SW128(off) ((off) ^ (((off) >> 3) & 0x70))

__device__ __forceinline__ void cp16(uint32_t dst, const void* src) {
    asm volatile("cp.async.cg.shared.global [%0], [%1], 16;" :: "r"(dst), "l"(src));
}
#define CP_COMMIT() asm volatile("cp.async.commit_group;" ::: "memory")
template <int N>
__device__ __forceinline__ void cp_wait() {
    asm volatile("cp.async.wait_group %0;" :: "n"(N) : "memory");
}

__device__ __forceinline__ void ldsm_x4(uint32_t* r, uint32_t addr) {
    asm volatile("ldmatrix.sync.aligned.m8n8.x4.shared.b16 {%0,%1,%2,%3}, [%4];"
                 : "=r"(r[0]), "=r"(r[1]), "=r"(r[2]), "=r"(r[3]) : "r"(addr));
}
__device__ __forceinline__ void ldsm_x2(uint32_t* r, uint32_t addr) {
    asm volatile("ldmatrix.sync.aligned.m8n8.x2.shared.b16 {%0,%1}, [%2];"
                 : "=r"(r[0]), "=r"(r[1]) : "r"(addr));
}
__device__ __forceinline__ void mma_bf16(float* d, const uint32_t* a, const uint32_t* b) {
    asm volatile(
        "mma.sync.aligned.m16n8k16.row.col.f32.bf16.bf16.f32 "
        "{%0,%1,%2,%3}, {%4,%5,%6,%7}, {%8,%9}, {%0,%1,%2,%3};"
        : "+f"(d[0]), "+f"(d[1]), "+f"(d[2]), "+f"(d[3])
        : "r"(a[0]), "r"(a[1]), "r"(a[2]), "r"(a[3]), "r"(b[0]), "r"(b[1]));
}

// ---------------------------------------------------------------------------
// Kernel 1: gather x_seq = W_xh[:, tok[t]]  (+ init all_h[0], reset flags)
// ---------------------------------------------------------------------------
__global__ void gather_kernel(const int* __restrict__ tok,
                              const float* __restrict__ Wxh,
                              const float* __restrict__ h0) {
    int i = blockIdx.x * blockDim.x + threadIdx.x;
    if (i < T_STEPS * HID) {
        int t = i / HID;
        int h = i - t * HID;
        g_xseq[i] = __ldg(&Wxh[(long long)h * VOC + tok[t]]);
    }
    if (i < HID)    g_allh[i]  = h0[i];
    if (i < G_CTAS) g_flags[i] = 0u;
}

// ---------------------------------------------------------------------------
// Kernel 2: persistent RNN scan (unchanged — correct & verified)
// ---------------------------------------------------------------------------
__global__ __launch_bounds__(256, 1)
void scan_kernel(const float* __restrict__ Whh,
                 const float* __restrict__ Bh) {
    __shared__ float hs[1024];
    const int g    = blockIdx.x;
    const int tid  = threadIdx.x;
    const int warp = tid >> 5;
    const int lane = tid & 31;
    const int row  = g * 8 + warp;

    float w[8][4];
#pragma unroll
    for (int j = 0; j < 8; j++)
#pragma unroll
        for (int q = 0; q < 4; q++) {
            int k = 4 * lane + q + 128 * j;
            w[j][q] = (k < HID) ? __ldg(&Whh[row * HID + k]) : 0.0f;
        }
    const float bias = __ldg(&Bh[row]);
    const float4* __restrict__ allh4 = (const float4*)g_allh;

    for (int t = 0; t < T_STEPS; t++) {
        if (t > 0 && tid < G_CTAS) {
            while (ld_acquire(&g_flags[tid]) < (unsigned)t) { }
        }
        __syncthreads();

        float xv = 0.0f;
        if (lane == 0) xv = __ldg(&g_xseq[t * HID + row]);

        if (tid < 250) {
            ((float4*)hs)[tid] = __ldcg(allh4 + (size_t)t * 250 + tid);
        } else {
            ((float4*)hs)[tid] = make_float4(0.f, 0.f, 0.f, 0.f);
        }
        __syncthreads();

        float a0 = 0.f, a1 = 0.f, a2 = 0.f, a3 = 0.f;
#pragma unroll
        for (int j = 0; j < 8; j++) {
            float4 hv = ((const float4*)hs)[lane + 32 * j];
            a0 = fmaf(w[j][0], hv.x, a0);
            a1 = fmaf(w[j][1], hv.y, a1);
            a2 = fmaf(w[j][2], hv.z, a2);
            a3 = fmaf(w[j][3], hv.w, a3);
        }
        float acc = (a0 + a1) + (a2 + a3);
#pragma unroll
        for (int s = 16; s > 0; s >>= 1)
            acc += __shfl_xor_sync(0xffffffffu, acc, s);

        if (lane == 0) {
            float y = tanhf(acc + xv + bias);
            g_allh[(size_t)(t + 1) * HID + row] = y;
        }
        __syncthreads();
        if (tid == 0) st_release(&g_flags[g], (unsigned)(t + 1));
    }
}

// ---------------------------------------------------------------------------
// Kernels 3a/3b: fp32 -> bf16 hi/lo split, augmented-K layout
//   A' rows: [Ah | Ah | Al],  B' rows: [Bh | Bl | Bh]
// ---------------------------------------------------------------------------
__global__ void convertA_kernel() {
    long long i = (long long)blockIdx.x * blockDim.x + threadIdx.x;
    if (i >= (long long)MPAD * KP) return;
    int m = (int)(i >> 10);
    int k = (int)(i & 1023);
    float v = (m < GM && k < HID) ? g_allh[(size_t)m * HID + k] : 0.0f;
    __nv_bfloat16 hi = __float2bfloat16(v);
    __nv_bfloat16 lo = __float2bfloat16(v - __bfloat162float(hi));
    size_t base = (size_t)m * KAUG + k;
    g_A2[base]        = hi;
    g_A2[base + 1024] = hi;
    g_A2[base + 2048] = lo;
}

__global__ void convertB_kernel(const float* __restrict__ Why) {
    long long i = (long long)blockIdx.x * blockDim.x + threadIdx.x;
    if (i >= (long long)VOC * KP) return;
    int n = (int)(i >> 10);
    int k = (int)(i & 1023);
    float v = (k < HID) ? Why[(size_t)n * HID + k] : 0.0f;
    __nv_bfloat16 hi = __float2bfloat16(v);
    __nv_bfloat16 lo = __float2bfloat16(v - __bfloat162float(hi));
    size_t base = (size_t)n * KAUG + k;
    g_B2[base]        = hi;
    g_B2[base + 1024] = lo;
    g_B2[base + 2048] = hi;
}

// ---------------------------------------------------------------------------
// Kernel 4: HMMA (mma.sync bf16) GEMM. C[4097,32000] = A'[Mx3072] @ B'[Nx3072]^T
// Tile 128x128, BK=64, 3-stage cp.async, 8 warps (2x4), warp tile 64x32.
// ---------------------------------------------------------------------------
#define MT 128
#define NT 128
#define KC 64
#define NCHUNK (KAUG / KC)          // 48
#define NSTAGE 3
#define A_BYTES (MT * 128)          // 16 KB
#define B_BYTES (NT * 128)          // 16 KB
#define STAGE_BYTES (A_BYTES + B_BYTES)
#define GEMM_SMEM (NSTAGE * STAGE_BYTES)   // 96 KB

__device__ __forceinline__ void load_chunk(int chunk, uint32_t stageA,
                                           int m0, int n0, int tid) {
    int k0 = chunk * KC;
    const char* Ag = (const char*)g_A2 + ((size_t)m0 * KAUG + k0) * 2;
    const char* Bg = (const char*)g_B2 + ((size_t)n0 * KAUG + k0) * 2;
    uint32_t stageB = stageA + A_BYTES;
#pragma unroll
    for (int q = 0; q < 4; q++) {                 // A: 1024 x 16B
        int idx = tid + 256 * q;
        int r = idx >> 3, c = idx & 7;
        uint32_t off = (uint32_t)(r * 128 + c * 16);
        cp16(stageA + SW128(off), Ag + (size_t)r * (KAUG * 2) + c * 16);
    }
#pragma unroll
    for (int q = 0; q < 4; q++) {                 // B: 1024 x 16B
        int idx = tid + 256 * q;
        int r = idx >> 3, c = idx & 7;
        uint32_t off = (uint32_t)(r * 128 + c * 16);
        cp16(stageB + SW128(off), Bg + (size_t)r * (KAUG * 2) + c * 16);
    }
    CP_COMMIT();
}

__global__ __launch_bounds__(256, 1)
void gemm_mma_kernel(float* __restrict__ C) {
    extern __shared__ char dsm[];
    const uint32_t base = smem_u32(dsm);

    const int tid  = threadIdx.x;
    const int wid  = tid >> 5;
    const int lane = tid & 31;
    const int wm   = wid >> 2;          // 0..1 -> rows wm*64
    const int wn   = wid & 3;           // 0..3 -> cols wn*32
    const int m0   = blockIdx.x * MT;
    const int n0   = blockIdx.y * NT;

    float acc[4][4][4];
#pragma unroll
    for (int i = 0; i < 4; i++)
#pragma unroll
        for (int j = 0; j < 4; j++)
#pragma unroll
            for (int q = 0; q < 4; q++) acc[i][j][q] = 0.f;

    // A ldmatrix address (per lane), relative within tile
    const uint32_t a_row = (uint32_t)(wm * 64 + (lane & 15));
    const uint32_t a_col = (uint32_t)((lane >> 4) * 8);
    const uint32_t b_row = (uint32_t)(wn * 32 + (lane & 7));
    const uint32_t b_col = (uint32_t)(((lane >> 3) & 1) * 8);

    // prologue
    load_chunk(0, base + 0 * STAGE_BYTES, m0, n0, tid);
    load_chunk(1, base + 1 * STAGE_BYTES, m0, n0, tid);

    for (int i = 0; i < NCHUNK; i++) {
        if (i == NCHUNK - 1) cp_wait<0>(); else cp_wait<1>();
        __syncthreads();

        if (i + 2 < NCHUNK) {
            int s = (i + 2) % NSTAGE;
            load_chunk(i + 2, base + s * STAGE_BYTES, m0, n0, tid);
        }

        const uint32_t sA = base + (i % NSTAGE) * STAGE_BYTES;
        const uint32_t sB = sA + A_BYTES;
#pragma unroll
        for (int ks = 0; ks < 4; ks++) {
            uint32_t a[4][4], b[4][2];
#pragma unroll
            for (int fm = 0; fm < 4; fm++) {
                uint32_t off = (a_row + fm * 16) * 128 + (a_col + ks * 16) * 2;
                ldsm_x4(a[fm], sA + SW128(off));
            }
#pragma unroll
            for (int fn = 0; fn < 4; fn++) {
                uint32_t off = (b_row + fn * 8) * 128 + (b_col + ks * 16) * 2;
                ldsm_x2(b[fn], sB + SW128(off));
            }
#pragma unroll
            for (int fm = 0; fm < 4; fm++)
#pragma unroll
                for (int fn = 0; fn < 4; fn++)
                    mma_bf16(acc[fm][fn], a[fm], b[fn]);
        }
    }

    // epilogue: direct register -> global stores
    const int er = lane >> 2;
    const int ec = (lane & 3) * 2;
#pragma unroll
    for (int fm = 0; fm < 4; fm++) {
        int r0 = m0 + wm * 64 + fm * 16 + er;
#pragma unroll
        for (int fn = 0; fn < 4; fn++) {
            int c = n0 + wn * 32 + fn * 8 + ec;
            if (r0 < GM)
                *(float2*)(C + (size_t)r0 * VOC + c) = make_float2(acc[fm][fn][0], acc[fm][fn][1]);
            if (r0 + 8 < GM)
                *(float2*)(C + (size_t)(r0 + 8) * VOC + c) = make_float2(acc[fm][fn][2], acc[fm][fn][3]);
        }
    }
}

// ---------------------------------------------------------------------------
extern "C" void kernel_launch(void* const* d_in, const int* in_sizes, int n_in,
                              void* d_out, int out_size) {
    const int*   tok = (const int*)  d_in[0];
    const float* h0  = (const float*)d_in[1];
    const float* Wxh = (const float*)d_in[2];
    const float* Whh = (const float*)d_in[3];
    const float* Why = (const float*)d_in[4];
    const float* Bh  = (const float*)d_in[5];
    float* out = (float*)d_out;

    gather_kernel<<<(T_STEPS * HID + 255) / 256, 256>>>(tok, Wxh, h0);
    convertB_kernel<<<(int)(((long long)VOC * KP + 255) / 256), 256>>>(Why);
    scan_kernel<<<G_CTAS, 256>>>(Whh, Bh);
    convertA_kernel<<<(int)(((long long)MPAD * KP + 255) / 256), 256>>>();

    cudaFuncSetAttribute(gemm_mma_kernel,
                         cudaFuncAttributeMaxDynamicSharedMemorySize, GEMM_SMEM);
    dim3 ggrid(MPAD / MT, VOC / NT);   // 33 x 250, m fastest (A' stays L2-resident)
    gemm_mma_kernel<<<ggrid, 256, GEMM_SMEM>>>(out);
}

// round 4
// speedup vs baseline: 2.2556x; 2.0113x over previous
#include <cuda_runtime.h>
#include <cuda_bf16.h>
#include <cstdint>

#define T_STEPS 4096
#define HID     1000
#define VOC     32000
#define G_CTAS  125
#define GM      4097
#define KP      1024
#define KAUG    3072            // 3 bf16 split terms
#define MPAD    4224            // 33 * 128
#define NBLKS   250             // 32000 / 128
#define MBLKS   33
#define NCHUNK  48              // KAUG / 64
#define TILE_B  16384           // 128 rows * 128 bytes (one chunk tile)

// ---------------- device scratch (allocation-free rule) ----------------
__device__ __align__(256)  float g_xseq[T_STEPS * HID];
__device__ __align__(256)  float g_allh[(T_STEPS + 1) * HID];
__device__ __align__(1024) char  g_A2T[(size_t)MBLKS * NCHUNK * TILE_B];   // 26 MB
__device__ __align__(1024) char  g_B2T[(size_t)NBLKS * NCHUNK * TILE_B];   // 197 MB
__device__ unsigned g_flags[G_CTAS * 32];   // one flag per 128B line

__device__ __forceinline__ unsigned ld_acquire(const unsigned* p) {
    unsigned v;
    asm volatile("ld.acquire.gpu.u32 %0, [%1];" : "=r"(v) : "l"(p) : "memory");
    return v;
}
__device__ __forceinline__ void st_release(unsigned* p, unsigned v) {
    asm volatile("st.release.gpu.u32 [%0], %1;" :: "l"(p), "r"(v) : "memory");
}
__device__ __forceinline__ uint32_t smem_u32(const void* p) {
    uint32_t a;
    asm("{ .reg .u64 t; cvta.to.shared.u64 t, %1; cvt.u32.u64 %0, t; }" : "=r"(a) : "l"(p));
    return a;
}
#define SW128(off) ((off) ^ (((off) >> 3) & 0x70))

#define MBAR_INIT(a, c) asm volatile("mbarrier.init.shared.b64 [%0], %1;" :: "r"(a), "r"(c) : "memory")
#define MBAR_ARRIVE(a)  asm volatile("mbarrier.arrive.shared.b64 _, [%0];" :: "r"(a) : "memory")
#define MBAR_EXPECT_TX(a, n) asm volatile("mbarrier.arrive.expect_tx.shared.b64 _, [%0], %1;" :: "r"(a), "r"(n) : "memory")
#define MBAR_WAIT(a, ph) do {                                                    \
    uint32_t _m = (a), _p = (ph), _d;                                            \
    asm volatile("{\n\t.reg .pred p;\n\t"                                        \
        "mbarrier.try_wait.parity.acquire.cta.shared::cta.b64 p, [%1], %2;\n\t"  \
        "selp.b32 %0, 1, 0, p;\n\t}" : "=r"(_d) : "r"(_m), "r"(_p) : "memory");  \
    if (!_d) {                                                                   \
        asm volatile("{\n\t.reg .pred P1;\n\tWL_%=:\n\t"                         \
            "mbarrier.try_wait.parity.acquire.cta.shared::cta.b64 P1, [%0], %1, 0x989680;\n\t" \
            "@P1 bra.uni WD_%=;\n\tbra.uni WL_%=;\n\tWD_%=:\n\t}"                \
            :: "r"(_m), "r"(_p) : "memory");                                     \
    }                                                                            \
} while (0)

__device__ __forceinline__ void bulk_cp(uint32_t dst, const void* src,
                                        uint32_t bytes, uint32_t mbar) {
    asm volatile(
        "cp.async.bulk.shared::cta.global.mbarrier::complete_tx::bytes [%0], [%1], %2, [%3];"
        :: "r"(dst), "l"(src), "r"(bytes), "r"(mbar) : "memory");
}
__device__ __forceinline__ void ldsm_x4(uint32_t* r, uint32_t addr) {
    asm volatile("ldmatrix.sync.aligned.m8n8.x4.shared.b16 {%0,%1,%2,%3}, [%4];"
                 : "=r"(r[0]), "=r"(r[1]), "=r"(r[2]), "=r"(r[3]) : "r"(addr));
}
__device__ __forceinline__ void ldsm_x2(uint32_t* r, uint32_t addr) {
    asm volatile("ldmatrix.sync.aligned.m8n8.x2.shared.b16 {%0,%1}, [%2];"
                 : "=r"(r[0]), "=r"(r[1]) : "r"(addr));
}
__device__ __forceinline__ void mma_bf16(float* d, const uint32_t* a, const uint32_t* b) {
    asm volatile(
        "mma.sync.aligned.m16n8k16.row.col.f32.bf16.bf16.f32 "
        "{%0,%1,%2,%3}, {%4,%5,%6,%7}, {%8,%9}, {%0,%1,%2,%3};"
        : "+f"(d[0]), "+f"(d[1]), "+f"(d[2]), "+f"(d[3])
        : "r"(a[0]), "r"(a[1]), "r"(a[2]), "r"(a[3]), "r"(b[0]), "r"(b[1]));
}

// ---------------------------------------------------------------------------
// Kernel 1: gather x_seq = W_xh[:, tok[t]]  (+ init all_h[0], reset flags)
// ---------------------------------------------------------------------------
__global__ void gather_kernel(const int* __restrict__ tok,
                              const float* __restrict__ Wxh,
                              const float* __restrict__ h0) {
    int i = blockIdx.x * blockDim.x + threadIdx.x;
    if (i < T_STEPS * HID) {
        int t = i / HID;
        int h = i - t * HID;
        g_xseq[i] = __ldg(&Wxh[(long long)h * VOC + tok[t]]);
    }
    if (i < HID)          g_allh[i]  = h0[i];
    if (i < G_CTAS * 32)  g_flags[i] = 0u;
}

// ---------------------------------------------------------------------------
// Kernel 2: persistent RNN scan.  Flags padded to one per 128B line.
// ---------------------------------------------------------------------------
__global__ __launch_bounds__(256, 1)
void scan_kernel(const float* __restrict__ Whh,
                 const float* __restrict__ Bh) {
    __shared__ float hs[1024];
    const int g    = blockIdx.x;
    const int tid  = threadIdx.x;
    const int warp = tid >> 5;
    const int lane = tid & 31;
    const int row  = g * 8 + warp;

    float w[8][4];
#pragma unroll
    for (int j = 0; j < 8; j++)
#pragma unroll
        for (int q = 0; q < 4; q++) {
            int k = 4 * lane + q + 128 * j;
            w[j][q] = (k < HID) ? __ldg(&Whh[row * HID + k]) : 0.0f;
        }
    const float bias = __ldg(&Bh[row]);
    const float4* __restrict__ allh4 = (const float4*)g_allh;

    for (int t = 0; t < T_STEPS; t++) {
        float xv = 0.0f;
        if (lane == 0) xv = __ldg(&g_xseq[t * HID + row]);   // prefetch before wait

        if (t > 0 && tid < G_CTAS) {
            while (ld_acquire(&g_flags[tid * 32]) < (unsigned)t) { }
        }
        __syncthreads();

        if (tid < 250) {
            ((float4*)hs)[tid] = __ldcg(allh4 + (size_t)t * 250 + tid);
        } else {
            ((float4*)hs)[tid] = make_float4(0.f, 0.f, 0.f, 0.f);
        }
        __syncthreads();

        float a0 = 0.f, a1 = 0.f, a2 = 0.f, a3 = 0.f;
#pragma unroll
        for (int j = 0; j < 8; j++) {
            float4 hv = ((const float4*)hs)[lane + 32 * j];
            a0 = fmaf(w[j][0], hv.x, a0);
            a1 = fmaf(w[j][1], hv.y, a1);
            a2 = fmaf(w[j][2], hv.z, a2);
            a3 = fmaf(w[j][3], hv.w, a3);
        }
        float acc = (a0 + a1) + (a2 + a3);
#pragma unroll
        for (int s = 16; s > 0; s >>= 1)
            acc += __shfl_xor_sync(0xffffffffu, acc, s);

        if (lane == 0) {
            float y = tanhf(acc + xv + bias);
            g_allh[(size_t)(t + 1) * HID + row] = y;
        }
        __syncthreads();
        if (tid == 0) st_release(&g_flags[g * 32], (unsigned)(t + 1));
    }
}

// ---------------------------------------------------------------------------
// Kernels 3a/3b: fp32 -> bf16 split into TILED PRE-SWIZZLED layout.
// Tile (blk, chunk) = 128 rows x 64 k-cols, 16KB, SW128-swizzled in gmem.
//   A' terms: [Ah | Ah | Al]   B' terms: [Bh | Bl | Bh]
// ---------------------------------------------------------------------------
__global__ void convertA_kernel() {
    long long i = (long long)blockIdx.x * blockDim.x + threadIdx.x;
    if (i >= (long long)MPAD * KAUG) return;
    int tileId = (int)(i >> 13);
    int e      = (int)(i & 8191);
    int r      = e >> 6;
    int c      = e & 63;
    int mblk   = tileId / NCHUNK;
    int chunk  = tileId - mblk * NCHUNK;
    int kp     = chunk * 64 + c;
    int term   = kp >> 10;
    int k      = kp & 1023;
    int m      = mblk * 128 + r;
    float v = (m < GM && k < HID) ? g_allh[(size_t)m * HID + k] : 0.0f;
    __nv_bfloat16 hi = __float2bfloat16(v);
    __nv_bfloat16 out = (term < 2) ? hi : __float2bfloat16(v - __bfloat162float(hi));
    uint32_t off = SW128((uint32_t)(r * 128 + c * 2));
    *(__nv_bfloat16*)(g_A2T + (size_t)tileId * TILE_B + off) = out;
}

__global__ void convertB_kernel(const float* __restrict__ Why) {
    long long i = (long long)blockIdx.x * blockDim.x + threadIdx.x;
    if (i >= (long long)VOC * KAUG) return;
    int tileId = (int)(i >> 13);
    int e      = (int)(i & 8191);
    int r      = e >> 6;
    int c      = e & 63;
    int nblk   = tileId / NCHUNK;
    int chunk  = tileId - nblk * NCHUNK;
    int kp     = chunk * 64 + c;
    int term   = kp >> 10;
    int k      = kp & 1023;
    int n      = nblk * 128 + r;
    float v = (k < HID) ? Why[(size_t)n * HID + k] : 0.0f;
    __nv_bfloat16 hi = __float2bfloat16(v);
    __nv_bfloat16 out = (term != 1) ? hi : __float2bfloat16(v - __bfloat162float(hi));
    uint32_t off = SW128((uint32_t)(r * 128 + c * 2));
    *(__nv_bfloat16*)(g_B2T + (size_t)tileId * TILE_B + off) = out;
}

// ---------------------------------------------------------------------------
// Kernel 4: HMMA GEMM fed by cp.async.bulk (1 instr / 16KB tile).
// Tile 128x128, KC=64, 4-stage mbarrier pipeline, warps 2x4, warp tile 64x32.
// ---------------------------------------------------------------------------
#define NSTAGE 4
#define STAGE_BYTES (2 * TILE_B)            // A 16KB + B 16KB
#define GEMM_SMEM (2048 + NSTAGE * STAGE_BYTES)

__global__ __launch_bounds__(256, 1)
void gemm_bulk_kernel(float* __restrict__ C) {
    extern __shared__ char dsm[];
    const uint32_t raw   = smem_u32(dsm);
    const uint32_t fullb = raw;                         // 4 x 8B
    const uint32_t emptb = raw + 64;                    // 4 x 8B
    const uint32_t tiles = (raw + 1024 + 1023) & ~1023u;

    const int tid  = threadIdx.x;
    const int wid  = tid >> 5;
    const int lane = tid & 31;
    const int wm   = wid >> 2;
    const int wn   = wid & 3;
    const int mblk = blockIdx.x;
    const int nblk = blockIdx.y;
    const int m0   = mblk * 128;
    const int n0   = nblk * 128;

    if (tid == 0) {
#pragma unroll
        for (int s = 0; s < NSTAGE; s++) {
            MBAR_INIT(fullb + 8 * s, 1);
            MBAR_INIT(emptb + 8 * s, 256);
        }
    }
    __syncthreads();

    const char* Abase = g_A2T + (size_t)mblk * NCHUNK * TILE_B;
    const char* Bbase = g_B2T + (size_t)nblk * NCHUNK * TILE_B;

    if (tid == 0) {
#pragma unroll
        for (int i = 0; i < NSTAGE; i++) {
            uint32_t mb = fullb + 8 * i;
            MBAR_EXPECT_TX(mb, STAGE_BYTES);
            bulk_cp(tiles + i * STAGE_BYTES,          Abase + (size_t)i * TILE_B, TILE_B, mb);
            bulk_cp(tiles + i * STAGE_BYTES + TILE_B, Bbase + (size_t)i * TILE_B, TILE_B, mb);
        }
    }

    float acc[4][4][4];
#pragma unroll
    for (int i = 0; i < 4; i++)
#pragma unroll
        for (int j = 0; j < 4; j++)
#pragma unroll
            for (int q = 0; q < 4; q++) acc[i][j][q] = 0.f;

    const uint32_t a_row = (uint32_t)(wm * 64 + (lane & 15));
    const uint32_t a_k   = (uint32_t)((lane >> 4) * 8);
    const uint32_t b_row = (uint32_t)(wn * 32 + (lane & 7));
    const uint32_t b_k   = (uint32_t)(((lane >> 3) & 1) * 8);

    for (int i = 0; i < NCHUNK; i++) {
        const int s = i & 3;
        MBAR_WAIT(fullb + 8 * s, (i >> 2) & 1);

        const uint32_t sA = tiles + s * STAGE_BYTES;
        const uint32_t sB = sA + TILE_B;
#pragma unroll
        for (int ks = 0; ks < 4; ks++) {
            uint32_t a[4][4], b[4][2];
#pragma unroll
            for (int fm = 0; fm < 4; fm++) {
                uint32_t off = (a_row + fm * 16) * 128 + (ks * 16 + a_k) * 2;
                ldsm_x4(a[fm], sA + SW128(off));
            }
#pragma unroll
            for (int fn = 0; fn < 4; fn++) {
                uint32_t off = (b_row + fn * 8) * 128 + (ks * 16 + b_k) * 2;
                ldsm_x2(b[fn], sB + SW128(off));
            }
#pragma unroll
            for (int fm = 0; fm < 4; fm++)
#pragma unroll
                for (int fn = 0; fn < 4; fn++)
                    mma_bf16(acc[fm][fn], a[fm], b[fn]);
        }
        MBAR_ARRIVE(emptb + 8 * s);

        if (tid == 0 && i + NSTAGE < NCHUNK) {
            MBAR_WAIT(emptb + 8 * s, (i >> 2) & 1);   // all 256 done with stage s
            const int j = i + NSTAGE;
            uint32_t mb = fullb + 8 * s;
            MBAR_EXPECT_TX(mb, STAGE_BYTES);
            bulk_cp(tiles + s * STAGE_BYTES,          Abase + (size_t)j * TILE_B, TILE_B, mb);
            bulk_cp(tiles + s * STAGE_BYTES + TILE_B, Bbase + (size_t)j * TILE_B, TILE_B, mb);
        }
    }

    // epilogue: direct register -> global stores
    const int er = lane >> 2;
    const int ec = (lane & 3) * 2;
#pragma unroll
    for (int fm = 0; fm < 4; fm++) {
        int r0 = m0 + wm * 64 + fm * 16 + er;
#pragma unroll
        for (int fn = 0; fn < 4; fn++) {
            int c = n0 + wn * 32 + fn * 8 + ec;
            if (r0 < GM)
                *(float2*)(C + (size_t)r0 * VOC + c) = make_float2(acc[fm][fn][0], acc[fm][fn][1]);
            if (r0 + 8 < GM)
                *(float2*)(C + (size_t)(r0 + 8) * VOC + c) = make_float2(acc[fm][fn][2], acc[fm][fn][3]);
        }
    }
}

// ---------------------------------------------------------------------------
extern "C" void kernel_launch(void* const* d_in, const int* in_sizes, int n_in,
                              void* d_out, int out_size) {
    const int*   tok = (const int*)  d_in[0];
    const float* h0  = (const float*)d_in[1];
    const float* Wxh = (const float*)d_in[2];
    const float* Whh = (const float*)d_in[3];
    const float* Why = (const float*)d_in[4];
    const float* Bh  = (const float*)d_in[5];
    float* out = (float*)d_out;

    gather_kernel<<<(T_STEPS * HID + 255) / 256, 256>>>(tok, Wxh, h0);
    convertB_kernel<<<(int)(((long long)VOC * KAUG + 255) / 256), 256>>>(Why);
    scan_kernel<<<G_CTAS, 256>>>(Whh, Bh);
    convertA_kernel<<<(int)(((long long)MPAD * KAUG + 255) / 256), 256>>>();

    cudaFuncSetAttribute(gemm_bulk_kernel,
                         cudaFuncAttributeMaxDynamicSharedMemorySize, GEMM_SMEM);
    dim3 ggrid(MBLKS, NBLKS);   // 33 x 250, m fastest (A' stays L2-resident)
    gemm_bulk_kernel<<<ggrid, 256, GEMM_SMEM>>>(out);
}